// round 17
// baseline (speedup 1.0000x reference)
#include <cuda_runtime.h>
#include <cuda_bf16.h>
#include <cuda_fp16.h>
#include <math.h>
#include <stdint.h>

#define S_LEN 4096
#define H_DIM 2048
#define HQ 8
#define HKV 4
#define HD 256
#define WIN 1024
#define NQK (HQ * HD + HKV * HD)   // 3072

// ================= portable PTX helpers =================
__device__ __forceinline__ uint32_t smem_u32(const void* p) {
    uint32_t a;
    asm("{ .reg .u64 t; cvta.to.shared.u64 t, %1; cvt.u32.u64 %0, t; }"
        : "=r"(a) : "l"(p));
    return a;
}

#define CP_ASYNC16(dst_u32, src_ptr) \
    asm volatile("cp.async.cg.shared.global [%0], [%1], 16;" \
                 :: "r"(dst_u32), "l"(src_ptr) : "memory")
#define CP_COMMIT() asm volatile("cp.async.commit_group;" ::: "memory")
#define CP_WAIT1()  asm volatile("cp.async.wait_group 1;" ::: "memory")

__device__ __forceinline__ void mma16816(float* d, const uint32_t* a,
                                         uint32_t b0, uint32_t b1) {
    asm volatile(
        "mma.sync.aligned.m16n8k16.row.col.f32.bf16.bf16.f32 "
        "{%0,%1,%2,%3}, {%4,%5,%6,%7}, {%8,%9}, {%0,%1,%2,%3};"
        : "+f"(d[0]), "+f"(d[1]), "+f"(d[2]), "+f"(d[3])
        : "r"(a[0]), "r"(a[1]), "r"(a[2]), "r"(a[3]), "r"(b0), "r"(b1));
}

__device__ __forceinline__ void mma16816h(float* d, const uint32_t* a,
                                          uint32_t b0, uint32_t b1) {
    asm volatile(
        "mma.sync.aligned.m16n8k16.row.col.f32.f16.f16.f32 "
        "{%0,%1,%2,%3}, {%4,%5,%6,%7}, {%8,%9}, {%0,%1,%2,%3};"
        : "+f"(d[0]), "+f"(d[1]), "+f"(d[2]), "+f"(d[3])
        : "r"(a[0]), "r"(a[1]), "r"(a[2]), "r"(a[3]), "r"(b0), "r"(b1));
}

__device__ __forceinline__ void mma16832s8(int* d, const uint32_t* a,
                                           uint32_t b0, uint32_t b1) {
    asm volatile(
        "mma.sync.aligned.m16n8k32.row.col.s32.s8.s8.s32 "
        "{%0,%1,%2,%3}, {%4,%5,%6,%7}, {%8,%9}, {%0,%1,%2,%3};"
        : "+r"(d[0]), "+r"(d[1]), "+r"(d[2]), "+r"(d[3])
        : "r"(a[0]), "r"(a[1]), "r"(a[2]), "r"(a[3]), "r"(b0), "r"(b1));
}

__device__ __forceinline__ void ldsm4(uint32_t* r, uint32_t addr) {
    asm volatile("ldmatrix.sync.aligned.m8n8.x4.shared.b16 {%0,%1,%2,%3}, [%4];"
                 : "=r"(r[0]), "=r"(r[1]), "=r"(r[2]), "=r"(r[3]) : "r"(addr));
}
__device__ __forceinline__ void ldsm4t(uint32_t* r, uint32_t addr) {
    asm volatile("ldmatrix.sync.aligned.m8n8.x4.trans.shared.b16 {%0,%1,%2,%3}, [%4];"
                 : "=r"(r[0]), "=r"(r[1]), "=r"(r[2]), "=r"(r[3]) : "r"(addr));
}

__device__ __forceinline__ uint32_t pack2h(float a, float b) {
    __half2 t = __floats2half2_rn(a, b);
    return *(uint32_t*)&t;
}

// inf-safe fast softcap: 50*tanh(x/50)
__device__ __forceinline__ float softcap50(float x) {
    float e = __expf(x * 0.04f);
    return 50.f * (1.f - __fdividef(2.f, e + 1.f));
}

// ================= scratch (device globals) =================
__device__ float g_QKp[S_LEN * NQK];
__device__ float g_Vp[S_LEN * (HKV * HD)];

// int8 two-digit operands + per-row scales
__device__ int8_t g_hq1[S_LEN * H_DIM];
__device__ int8_t g_hq2[S_LEN * H_DIM];
__device__ float  g_sh[S_LEN];
__device__ int8_t g_wqk1[NQK * H_DIM];
__device__ int8_t g_wqk2[NQK * H_DIM];
__device__ float  g_swqk[NQK];
__device__ int8_t g_wv1[HKV * HD * H_DIM];
__device__ int8_t g_wv2[HKV * HD * H_DIM];
__device__ float  g_swv[HKV * HD];

__device__ __half g_wo_f[H_DIM * HQ * HD];
__device__ __half g_ao_fh[S_LEN * HQ * HD];
__device__ __half g_ao_fl[S_LEN * HQ * HD];

__device__ __nv_bfloat16 g_qr_h[HQ * S_LEN * HD];
__device__ __nv_bfloat16 g_qr_l[HQ * S_LEN * HD];
__device__ __nv_bfloat16 g_kr_h[HKV * S_LEN * HD];
__device__ __nv_bfloat16 g_kr_l[HKV * S_LEN * HD];
__device__ __half        g_vr_f[HKV * S_LEN * HD];

// ====== wo -> fp16 (elementwise) ======
#define N4_WO (H_DIM * HQ * HD / 4)
__global__ __launch_bounds__(256)
void cvt_wo(const float4* __restrict__ wo, __half* __restrict__ wof) {
    int i = blockIdx.x * blockDim.x + threadIdx.x;
    if (i >= N4_WO) return;
    float4 v = wo[i];
    union { ushort4 u; __half b[4]; } H;
    H.b[0] = __float2half_rn(v.x); H.b[1] = __float2half_rn(v.y);
    H.b[2] = __float2half_rn(v.z); H.b[3] = __float2half_rn(v.w);
    *(ushort4*)(wof + 4 * (size_t)i) = H.u;
}

// ====== row quantization: x ~ s * (128*d1 + d2), s = rowmax/16255 ======
#define QROWS (S_LEN + NQK + HKV * HD)
__global__ __launch_bounds__(256)
void quant_rows(const float* __restrict__ hid, const float* __restrict__ wq,
                const float* __restrict__ wk, const float* __restrict__ wv,
                int8_t* __restrict__ hq1, int8_t* __restrict__ hq2, float* __restrict__ sh,
                int8_t* __restrict__ wqk1, int8_t* __restrict__ wqk2, float* __restrict__ swqk,
                int8_t* __restrict__ wv1, int8_t* __restrict__ wv2, float* __restrict__ swv) {
    const int row = blockIdx.x;
    const int t = threadIdx.x;
    const float* src;
    int8_t *d1, *d2;
    float* sp;
    if (row < S_LEN) {
        src = hid + (size_t)row * H_DIM;
        d1 = hq1 + (size_t)row * H_DIM; d2 = hq2 + (size_t)row * H_DIM;
        sp = sh + row;
    } else if (row < S_LEN + HQ * HD) {
        int r = row - S_LEN;
        src = wq + (size_t)r * H_DIM;
        d1 = wqk1 + (size_t)r * H_DIM; d2 = wqk2 + (size_t)r * H_DIM;
        sp = swqk + r;
    } else if (row < S_LEN + NQK) {
        int r = row - S_LEN - HQ * HD;
        src = wk + (size_t)r * H_DIM;
        d1 = wqk1 + (size_t)(HQ * HD + r) * H_DIM;
        d2 = wqk2 + (size_t)(HQ * HD + r) * H_DIM;
        sp = swqk + HQ * HD + r;
    } else {
        int r = row - S_LEN - NQK;
        src = wv + (size_t)r * H_DIM;
        d1 = wv1 + (size_t)r * H_DIM; d2 = wv2 + (size_t)r * H_DIM;
        sp = swv + r;
    }

    float x[8];
    float m = 0.f;
#pragma unroll
    for (int j = 0; j < 8; j++) {
        x[j] = src[t + 256 * j];
        m = fmaxf(m, fabsf(x[j]));
    }
#pragma unroll
    for (int off = 16; off > 0; off >>= 1)
        m = fmaxf(m, __shfl_xor_sync(0xffffffffu, m, off));
    __shared__ float red[8];
    if ((t & 31) == 0) red[t >> 5] = m;
    __syncthreads();
    m = red[0];
#pragma unroll
    for (int r = 1; r < 8; r++) m = fmaxf(m, red[r]);

    const float inv = (m > 0.f) ? __fdividef(16255.f, m) : 0.f;
    if (t == 0) *sp = (m > 0.f) ? m * (1.0f / 16255.f) : 0.f;
#pragma unroll
    for (int j = 0; j < 8; j++) {
        float q = x[j] * inv;
        float x1 = rintf(q * 0.0078125f);         // /128
        float x2 = rintf(q - 128.f * x1);          // in [-64, 64]
        d1[t + 256 * j] = (int8_t)(int)x1;
        d2[t + 256 * j] = (int8_t)(int)x2;
    }
}

// swizzle for 64B-pitch stages
__device__ __forceinline__ uint32_t gsw(int r, int c) {
    return (uint32_t)(r * 64 + ((c ^ (r & 3)) * 16));
}

// ============ int8 3-term GEMM: C = sA[m]*sB[n]*(16384*A1B1 + 128*(A1B2+A2B1))
// CTA 64x128, 128 threads, warp 32x64, BK=64 int8 (64B rows), 3-stage, 2 CTA/SM.
#define G_MATA 4096
#define G_MATB 8192
#define G_A_1 0
#define G_A_2 4096
#define G_B_1 8192
#define G_B_2 16384
#define G_SS  24576
#define SMEM_GEMM (3 * G_SS)

__global__ __launch_bounds__(128, 2)
void gemm_s8x3(const int8_t* __restrict__ A1, const int8_t* __restrict__ A2,
               const int8_t* __restrict__ B1, const int8_t* __restrict__ B2,
               const float* __restrict__ sA, const float* __restrict__ sB,
               float* __restrict__ C, int N, int K) {
    extern __shared__ char smemc[];
    const uint32_t sb = smem_u32(smemc);
    const int tid = threadIdx.x;
    const int lane = tid & 31;
    const int w = tid >> 5;
    const int wm = (w >> 1) * 32;
    const int wn = (w & 1) * 64;
    const int bm = blockIdx.y * 64;
    const int bn = blockIdx.x * 128;
    const int nkb = K / 64;          // 64 int8 elements (=64B) per stage row

    auto load_stage = [&](int s, int kblk) {
        const uint32_t st = sb + s * G_SS;
#pragma unroll
        for (int m = 0; m < 2; m++) {
            const int8_t* src = (m ? A2 : A1) + (size_t)bm * K + kblk;
            const uint32_t dstb = st + G_A_1 + m * G_MATA;
#pragma unroll
            for (int i = 0; i < 2; i++) {
                int flat = tid + i * 128;
                int r = flat >> 2, c = flat & 3;
                CP_ASYNC16(dstb + gsw(r, c), src + (size_t)r * K + c * 16);
            }
        }
#pragma unroll
        for (int m = 0; m < 2; m++) {
            const int8_t* src = (m ? B2 : B1) + (size_t)bn * K + kblk;
            const uint32_t dstb = st + G_B_1 + m * G_MATB;
#pragma unroll
            for (int i = 0; i < 4; i++) {
                int flat = tid + i * 128;
                int r = flat >> 2, c = flat & 3;
                CP_ASYNC16(dstb + gsw(r, c), src + (size_t)r * K + c * 16);
            }
        }
    };

    int acc1[2][8][4], acc2[2][8][4];
#pragma unroll
    for (int i = 0; i < 2; i++)
#pragma unroll
        for (int j = 0; j < 8; j++)
#pragma unroll
            for (int q = 0; q < 4; q++) { acc1[i][j][q] = 0; acc2[i][j][q] = 0; }

    load_stage(0, 0);   CP_COMMIT();
    load_stage(1, 64);  CP_COMMIT();
    load_stage(2, 128); CP_COMMIT();

    const int aro = (lane & 7) + 8 * ((lane >> 3) & 1);
    const int acs = (lane >> 4);
    const int bro = (lane & 7) + 8 * ((lane >> 4) & 1);
    const int bcs = ((lane >> 3) & 1);

    int s = 0;
    for (int kb = 0; kb < nkb; kb++) {
        CP_WAIT1();
        __syncthreads();
        if (kb >= 1 && kb + 2 < nkb) load_stage((kb + 2) % 3, (kb + 2) * 64);
        if (kb >= 1) CP_COMMIT();
        const uint32_t st = sb + s * G_SS;

#pragma unroll
        for (int kk = 0; kk < 2; kk++) {       // each kk = 32B = k32
            uint32_t a1[2][4], a2[2][4];
#pragma unroll
            for (int i = 0; i < 2; i++) {
                int r = wm + i * 16 + aro;
                uint32_t ab = st + G_A_1 + gsw(r, kk * 2 + acs);
                ldsm4(a1[i], ab);
                ldsm4(a2[i], ab + G_MATA);
            }
#pragma unroll
            for (int jp = 0; jp < 4; jp++) {
                uint32_t b1[4], b2[4];
                int r = wn + jp * 16 + bro;
                uint32_t bb = st + G_B_1 + gsw(r, kk * 2 + bcs);
                ldsm4(b1, bb);
                ldsm4(b2, bb + G_MATB);
#pragma unroll
                for (int i = 0; i < 2; i++) {
                    mma16832s8(acc1[i][2 * jp],     a1[i], b1[0], b1[1]);
                    mma16832s8(acc1[i][2 * jp + 1], a1[i], b1[2], b1[3]);
                }
#pragma unroll
                for (int i = 0; i < 2; i++) {
                    mma16832s8(acc2[i][2 * jp],     a1[i], b2[0], b2[1]);
                    mma16832s8(acc2[i][2 * jp + 1], a1[i], b2[2], b2[3]);
                }
#pragma unroll
                for (int i = 0; i < 2; i++) {
                    mma16832s8(acc2[i][2 * jp],     a2[i], b1[0], b1[1]);
                    mma16832s8(acc2[i][2 * jp + 1], a2[i], b1[2], b1[3]);
                }
            }
        }
        s = (s == 2) ? 0 : s + 1;
    }

    const int lr = lane >> 2;
    const int lc = lane & 3;
#pragma unroll
    for (int i = 0; i < 2; i++) {
        const int r0 = bm + wm + i * 16 + lr;
        const float sa0 = sA[r0];
        const float sa1 = sA[r0 + 8];
#pragma unroll
        for (int j = 0; j < 8; j++) {
            const int c0 = bn + wn + j * 8 + lc * 2;
            const float sb0 = sB[c0];
            const float sb1 = sB[c0 + 1];
            float v0 = sa0 * sb0 * (16384.f * (float)acc1[i][j][0] + 128.f * (float)acc2[i][j][0]);
            float v1 = sa0 * sb1 * (16384.f * (float)acc1[i][j][1] + 128.f * (float)acc2[i][j][1]);
            float v2 = sa1 * sb0 * (16384.f * (float)acc1[i][j][2] + 128.f * (float)acc2[i][j][2]);
            float v3 = sa1 * sb1 * (16384.f * (float)acc1[i][j][3] + 128.f * (float)acc2[i][j][3]);
            *(float2*)(C + (size_t)r0 * N + c0) = make_float2(v0, v1);
            *(float2*)(C + (size_t)(r0 + 8) * N + c0) = make_float2(v2, v3);
        }
    }
}

// ============ fp16 2-term GEMM (output projection) ====================
#define F_A_H 0
#define F_A_L 4096
#define F_B   8192
#define F_SS  16384
#define SMEM_GEMM_F (3 * F_SS)

__global__ __launch_bounds__(128, 3)
void gemm_fp16x2(const __half* __restrict__ Ah, const __half* __restrict__ Al,
                 const __half* __restrict__ B,
                 float* __restrict__ C, int N, int K) {
    extern __shared__ char smemc[];
    const uint32_t sb = smem_u32(smemc);
    const int tid = threadIdx.x;
    const int lane = tid & 31;
    const int w = tid >> 5;
    const int wm = (w >> 1) * 32;
    const int wn = (w & 1) * 64;
    const int bm = blockIdx.y * 64;
    const int bn = blockIdx.x * 128;
    const int nkb = K / 32;

    auto load_stage = [&](int s, int kblk) {
        const uint32_t st = sb + s * F_SS;
#pragma unroll
        for (int m = 0; m < 2; m++) {
            const __half* src = (m ? Al : Ah) + (size_t)bm * K + kblk;
            const uint32_t dstb = st + F_A_H + m * 4096;
#pragma unroll
            for (int i = 0; i < 2; i++) {
                int flat = tid + i * 128;
                int r = flat >> 2, c = flat & 3;
                CP_ASYNC16(dstb + gsw(r, c), src + (size_t)r * K + c * 8);
            }
        }
        {
            const __half* src = B + (size_t)bn * K + kblk;
            const uint32_t dstb = st + F_B;
#pragma unroll
            for (int i = 0; i < 4; i++) {
                int flat = tid + i * 128;
                int r = flat >> 2, c = flat & 3;
                CP_ASYNC16(dstb + gsw(r, c), src + (size_t)r * K + c * 8);
            }
        }
    };

    float acc[2][8][4];
#pragma unroll
    for (int i = 0; i < 2; i++)
#pragma unroll
        for (int j = 0; j < 8; j++)
#pragma unroll
            for (int q = 0; q < 4; q++) acc[i][j][q] = 0.f;

    load_stage(0, 0);  CP_COMMIT();
    load_stage(1, 32); CP_COMMIT();
    load_stage(2, 64); CP_COMMIT();

    const int aro = (lane & 7) + 8 * ((lane >> 3) & 1);
    const int acs = (lane >> 4);
    const int bro = (lane & 7) + 8 * ((lane >> 4) & 1);
    const int bcs = ((lane >> 3) & 1);

    int s = 0;
    for (int kb = 0; kb < nkb; kb++) {
        CP_WAIT1();
        __syncthreads();
        if (kb >= 1 && kb + 2 < nkb) load_stage((kb + 2) % 3, (kb + 2) * 32);
        if (kb >= 1) CP_COMMIT();
        const uint32_t st = sb + s * F_SS;

#pragma unroll
        for (int kk = 0; kk < 2; kk++) {
            uint32_t ah[2][4], al[2][4];
#pragma unroll
            for (int i = 0; i < 2; i++) {
                int r = wm + i * 16 + aro;
                uint32_t ab = st + F_A_H + gsw(r, kk * 2 + acs);
                ldsm4(ah[i], ab);
                ldsm4(al[i], ab + 4096);
            }
#pragma unroll
            for (int jp = 0; jp < 4; jp++) {
                uint32_t bh[4];
                int r = wn + jp * 16 + bro;
                ldsm4(bh, st + F_B + gsw(r, kk * 2 + bcs));
#pragma unroll
                for (int i = 0; i < 2; i++) {
                    mma16816h(acc[i][2 * jp],     ah[i], bh[0], bh[1]);
                    mma16816h(acc[i][2 * jp + 1], ah[i], bh[2], bh[3]);
                }
#pragma unroll
                for (int i = 0; i < 2; i++) {
                    mma16816h(acc[i][2 * jp],     al[i], bh[0], bh[1]);
                    mma16816h(acc[i][2 * jp + 1], al[i], bh[2], bh[3]);
                }
            }
        }
        s = (s == 2) ? 0 : s + 1;
    }

    const int lr = lane >> 2;
    const int lc = lane & 3;
#pragma unroll
    for (int i = 0; i < 2; i++) {
        const int r0 = bm + wm + i * 16 + lr;
#pragma unroll
        for (int j = 0; j < 8; j++) {
            const int c0 = bn + wn + j * 8 + lc * 2;
            *(float2*)(C + (size_t)r0 * N + c0) = make_float2(acc[i][j][0], acc[i][j][1]);
            *(float2*)(C + (size_t)(r0 + 8) * N + c0) = make_float2(acc[i][j][2], acc[i][j][3]);
        }
    }
}

// ======= RMSNorm + RoPE, warp-per-head, sync-free ============
__global__ __launch_bounds__(256)
void norm_rope3(const float* __restrict__ QKp, const float* __restrict__ Vp,
                const float* __restrict__ cosb, const float* __restrict__ sinb,
                const float* __restrict__ qw, const float* __restrict__ kw,
                __nv_bfloat16* __restrict__ Qrh, __nv_bfloat16* __restrict__ Qrl,
                __nv_bfloat16* __restrict__ Krh, __nv_bfloat16* __restrict__ Krl,
                __half* __restrict__ Vrf) {
    const int s = blockIdx.x;
    const int w = threadIdx.x >> 5;
    const int lane = threadIdx.x & 31;

#pragma unroll
    for (int it = 0; it < 2; it++) {
        const int slot = it * 8 + w;
        const float* src;
        const float* wp = nullptr;
        if (slot < HQ) {
            src = QKp + (size_t)s * NQK + slot * HD;
            wp = qw;
        } else if (slot < HQ + HKV) {
            src = QKp + (size_t)s * NQK + HQ * HD + (slot - HQ) * HD;
            wp = kw;
        } else {
            src = Vp + (size_t)s * (HKV * HD) + (slot - HQ - HKV) * HD;
        }

        float y[8];
        float v = 0.f;
#pragma unroll
        for (int j = 0; j < 8; j++) {
            y[j] = src[lane + 32 * j];
            v += y[j] * y[j];
        }
#pragma unroll
        for (int off = 16; off > 0; off >>= 1)
            v += __shfl_xor_sync(0xffffffffu, v, off);
        const float rms = rsqrtf(v * (1.0f / HD) + 1e-6f);
#pragma unroll
        for (int j = 0; j < 8; j++) y[j] *= rms;

        if (slot < HQ + HKV) {
#pragma unroll
            for (int j = 0; j < 8; j++) y[j] *= wp[lane + 32 * j];
            float yr[8];
#pragma unroll
            for (int j = 0; j < 8; j++) yr[j] = (j < 4) ? -y[j + 4] : y[j - 4];
#pragma unroll
            for (int j = 0; j < 8; j++) {
                int d = lane + 32 * j;
                y[j] = y[j] * cosb[(size_t)s * HD + d] + yr[j] * sinb[(size_t)s * HD + d];
            }
            __nv_bfloat16* dh;
            __nv_bfloat16* dl;
            if (slot < HQ) {
                dh = Qrh + ((size_t)slot * S_LEN + s) * HD;
                dl = Qrl + ((size_t)slot * S_LEN + s) * HD;
            } else {
                dh = Krh + ((size_t)(slot - HQ) * S_LEN + s) * HD;
                dl = Krl + ((size_t)(slot - HQ) * S_LEN + s) * HD;
            }
#pragma unroll
            for (int j = 0; j < 8; j++) {
                __nv_bfloat16 hb = __float2bfloat16(y[j]);
                dh[lane + 32 * j] = hb;
                dl[lane + 32 * j] = __float2bfloat16(y[j] - __bfloat162float(hb));
            }
        } else {
            __half* dv = Vrf + ((size_t)(slot - HQ - HKV) * S_LEN + s) * HD;
#pragma unroll
            for (int j = 0; j < 8; j++)
                dv[lane + 32 * j] = __float2half_rn(y[j]);
        }
    }
}

// ================= HMMA flash attention (sliding window + softcap) =========
#define APITCH 528
#define AQH_OFF 0
#define AQL_OFF 33792
#define AKH_OFF 67584
#define AKL_OFF 101376
#define AVF_OFF 135168
#define APH_OFF 168960
#define APL_OFF 178176
#define ASTAT_OFF 187392
#define SMEM_ATTN 189184

__global__ __launch_bounds__(256, 1)
void attn_mma(const __nv_bfloat16* __restrict__ Qh, const __nv_bfloat16* __restrict__ Ql,
              const __nv_bfloat16* __restrict__ Kh, const __nv_bfloat16* __restrict__ Kl,
              const __half* __restrict__ Vf,
              __half* __restrict__ AOh, __half* __restrict__ AOl) {
    extern __shared__ char smemc[];
    const uint32_t sb = smem_u32(smemc);
    const int tid = threadIdx.x;
    const int lane = tid & 31;
    const int w = tid >> 5;
    const int h = blockIdx.y;
    const int q0 = (gridDim.x - 1 - blockIdx.x) * 64;   // heavy-first

    const __nv_bfloat16* qhp = Qh + ((size_t)h * S_LEN + q0) * HD;
    const __nv_bfloat16* qlp = Ql + ((size_t)h * S_LEN + q0) * HD;
    const __nv_bfloat16* khp = Kh + (size_t)(h >> 1) * S_LEN * HD;
    const __nv_bfloat16* klp = Kl + (size_t)(h >> 1) * S_LEN * HD;
    const __half* vfp = Vf + (size_t)(h >> 1) * S_LEN * HD;

    float* marr  = (float*)(smemc + ASTAT_OFF);
    float* larr  = marr + 64;
    float* alpha = marr + 128;
    float* pm0   = marr + 192;
    float* pm1   = marr + 256;
    float* ps0   = marr + 320;
    float* ps1   = marr + 384;

    if (tid < 64) { marr[tid] = -1e30f; larr[tid] = 0.f; }

    auto cpQ = [&](uint32_t off, const __nv_bfloat16* src) {
#pragma unroll
        for (int i = 0; i < 8; i++) {
            int flat = tid + i * 256;
            int r = flat >> 5, c = flat & 31;
            CP_ASYNC16(sb + off + r * APITCH + c * 16, src + (size_t)r * HD + c * 8);
        }
    };
    auto cpT = [&](uint32_t off, const __nv_bfloat16* base, int kt) {
#pragma unroll
        for (int i = 0; i < 8; i++) {
            int flat = tid + i * 256;
            int r = flat >> 5, c = flat & 31;
            CP_ASYNC16(sb + off + r * APITCH + c * 16, base + (size_t)(kt + r) * HD + c * 8);
        }
    };
    auto cpV = [&](int kt) {
#pragma unroll
        for (int i = 0; i < 8; i++) {
            int flat = tid + i * 256;
            int r = flat >> 5, c = flat & 31;
            CP_ASYNC16(sb + AVF_OFF + r * APITCH + c * 16, vfp + (size_t)(kt + r) * HD + c * 8);
        }
    };

    int klo = q0 - (WIN - 1);
    if (klo < 0) klo = 0;
    const int kt0 = klo & ~63;

    cpQ(AQH_OFF, qhp); cpQ(AQL_OFF, qlp);
    cpT(AKH_OFF, khp, kt0); cpT(AKL_OFF, klp, kt0);
    CP_COMMIT();

    float oacc[16][4];
#pragma unroll
    for (int i = 0; i < 16; i++)
#pragma unroll
        for (int q = 0; q < 4; q++) oacc[i][q] = 0.f;

    const int aro = (lane & 7) + 8 * ((lane >> 3) & 1);
    const int aco = (lane >> 4) * 16;
    const int bro = (lane & 7) + 8 * ((lane >> 4) & 1);
    const int bco = ((lane >> 3) & 1) * 16;
    const int R  = 16 * (w >> 1);
    const int Ch = 32 * (w & 1);
    const int Rp = 16 * (w & 3);
    const int Dq = 128 * (w >> 2);
    const int rl = lane >> 2;

    __syncthreads();

    for (int kt = kt0; kt <= q0; kt += 64) {
        cpV(kt);
        CP_COMMIT();
        CP_WAIT1();
        __syncthreads();

        // ---------------- QK (bf16 3-term) ----------------
        float sacc[4][4];
#pragma unroll
        for (int i = 0; i < 4; i++)
#pragma unroll
            for (int q = 0; q < 4; q++) sacc[i][q] = 0.f;

#pragma unroll
        for (int ks = 0; ks < 16; ks++) {
            uint32_t aH[4], aL[4];
            uint32_t ab = sb + AQH_OFF + (R + aro) * APITCH + ks * 32 + aco;
            ldsm4(aH, ab);
            ldsm4(aL, ab + (AQL_OFF - AQH_OFF));
            uint32_t bH0[4], bL0[4], bH1[4], bL1[4];
            uint32_t bb0 = sb + AKH_OFF + (Ch + bro) * APITCH + ks * 32 + bco;
            uint32_t bb1 = sb + AKH_OFF + (Ch + 16 + bro) * APITCH + ks * 32 + bco;
            ldsm4(bH0, bb0);
            ldsm4(bL0, bb0 + (AKL_OFF - AKH_OFF));
            ldsm4(bH1, bb1);
            ldsm4(bL1, bb1 + (AKL_OFF - AKH_OFF));
            mma16816(sacc[0], aH, bH0[0], bH0[1]);
            mma16816(sacc[1], aH, bH0[2], bH0[3]);
            mma16816(sacc[2], aH, bH1[0], bH1[1]);
            mma16816(sacc[3], aH, bH1[2], bH1[3]);
            mma16816(sacc[0], aH, bL0[0], bL0[1]);
            mma16816(sacc[1], aH, bL0[2], bL0[3]);
            mma16816(sacc[2], aH, bL1[0], bL1[1]);
            mma16816(sacc[3], aH, bL1[2], bL1[3]);
            mma16816(sacc[0], aL, bH0[0], bH0[1]);
            mma16816(sacc[1], aL, bH0[2], bH0[3]);
            mma16816(sacc[2], aL, bH1[0], bH1[1]);
            mma16816(sacc[3], aL, bH1[2], bH1[3]);
        }

        const int rlo = R + rl, rhi = R + rl + 8;
        float mx0 = -1e30f, mx1 = -1e30f;
#pragma unroll
        for (int n8 = 0; n8 < 4; n8++) {
#pragma unroll
            for (int e = 0; e < 4; e++) {
                int row = (e < 2) ? rlo : rhi;
                int kg = kt + Ch + n8 * 8 + (lane & 3) * 2 + (e & 1);
                int qg = q0 + row;
                float s = softcap50(sacc[n8][e]);
                bool ok = (kg <= qg) && (qg - kg < WIN);
                s = ok ? s : -1e30f;
                sacc[n8][e] = s;
                if (e < 2) mx0 = fmaxf(mx0, s); else mx1 = fmaxf(mx1, s);
            }
        }
        mx0 = fmaxf(mx0, __shfl_xor_sync(0xffffffffu, mx0, 1));
        mx0 = fmaxf(mx0, __shfl_xor_sync(0xffffffffu, mx0, 2));
        mx1 = fmaxf(mx1, __shfl_xor_sync(0xffffffffu, mx1, 1));
        mx1 = fmaxf(mx1, __shfl_xor_sync(0xffffffffu, mx1, 2));
        if ((lane & 3) == 0) {
            float* pmh = (w & 1) ? pm1 : pm0;
            pmh[rlo] = mx0; pmh[rhi] = mx1;
        }
        __syncthreads();

        if (kt + 64 <= q0) { cpT(AKH_OFF, khp, kt + 64); cpT(AKL_OFF, klp, kt + 64); }
        CP_COMMIT();

        if (tid < 64) {
            float mo = marr[tid];
            float mn = fmaxf(mo, fmaxf(pm0[tid], pm1[tid]));
            alpha[tid] = (mn > -1e29f) ? __expf(mo - mn) : 1.f;
            marr[tid] = mn;
        }
        __syncthreads();

        {
            float mn0 = marr[rlo], mn1 = marr[rhi];
            float sum0 = 0.f, sum1 = 0.f;
#pragma unroll
            for (int n8 = 0; n8 < 4; n8++) {
                float p0 = (sacc[n8][0] > -1e29f) ? __expf(sacc[n8][0] - mn0) : 0.f;
                float p1 = (sacc[n8][1] > -1e29f) ? __expf(sacc[n8][1] - mn0) : 0.f;
                float p2 = (sacc[n8][2] > -1e29f) ? __expf(sacc[n8][2] - mn1) : 0.f;
                float p3 = (sacc[n8][3] > -1e29f) ? __expf(sacc[n8][3] - mn1) : 0.f;
                sum0 += p0 + p1; sum1 += p2 + p3;
                int cb = (Ch + n8 * 8 + (lane & 3) * 2) * 2;
                uint32_t hlo = pack2h(p0, p1);
                uint32_t hhi = pack2h(p2, p3);
                __half2 hv0 = *(__half2*)&hlo;
                __half2 hv1 = *(__half2*)&hhi;
                *(uint32_t*)(smemc + APH_OFF + rlo * 144 + cb) = hlo;
                *(uint32_t*)(smemc + APH_OFF + rhi * 144 + cb) = hhi;
                *(uint32_t*)(smemc + APL_OFF + rlo * 144 + cb) =
                    pack2h(p0 - __half2float(hv0.x), p1 - __half2float(hv0.y));
                *(uint32_t*)(smemc + APL_OFF + rhi * 144 + cb) =
                    pack2h(p2 - __half2float(hv1.x), p3 - __half2float(hv1.y));
            }
            sum0 += __shfl_xor_sync(0xffffffffu, sum0, 1);
            sum0 += __shfl_xor_sync(0xffffffffu, sum0, 2);
            sum1 += __shfl_xor_sync(0xffffffffu, sum1, 1);
            sum1 += __shfl_xor_sync(0xffffffffu, sum1, 2);
            if ((lane & 3) == 0) {
                float* psh = (w & 1) ? ps1 : ps0;
                psh[rlo] = sum0; psh[rhi] = sum1;
            }
        }
        __syncthreads();
        if (tid < 64) larr[tid] = alpha[tid] * larr[tid] + ps0[tid] + ps1[tid];
        CP_WAIT1();
        __syncthreads();

        // ---------------- PV (fp16 2-term) ----------------
        {
            float a0 = alpha[Rp + rl], a1 = alpha[Rp + 8 + rl];
#pragma unroll
            for (int n8 = 0; n8 < 16; n8++) {
                oacc[n8][0] *= a0; oacc[n8][1] *= a0;
                oacc[n8][2] *= a1; oacc[n8][3] *= a1;
            }
            const int vco = ((lane >> 4) & 1) * 8;
            const int vrw = (lane & 7) + 8 * ((lane >> 3) & 1);
#pragma unroll
            for (int ks = 0; ks < 4; ks++) {
                uint32_t pH[4], pL[4];
                uint32_t pb = sb + APH_OFF + (Rp + aro) * 144 + ks * 32 + aco;
                ldsm4(pH, pb);
                ldsm4(pL, pb + (APL_OFF - APH_OFF));
#pragma unroll
                for (int dt = 0; dt < 8; dt += 2) {
                    uint32_t vH0[4], vH1[4];
                    uint32_t vb0 = sb + AVF_OFF + (ks * 16 + vrw) * APITCH +
                                   (Dq + dt * 16 + vco) * 2;
                    uint32_t vb1 = vb0 + 32;
                    ldsm4t(vH0, vb0);
                    ldsm4t(vH1, vb1);
                    mma16816h(oacc[2 * dt],     pH, vH0[0], vH0[1]);
                    mma16816h(oacc[2 * dt + 1], pH, vH0[2], vH0[3]);
                    mma16816h(oacc[2 * dt + 2], pH, vH1[0], vH1[1]);
                    mma16816h(oacc[2 * dt + 3], pH, vH1[2], vH1[3]);
                    mma16816h(oacc[2 * dt],     pL, vH0[0], vH0[1]);
                    mma16816h(oacc[2 * dt + 1], pL, vH0[2], vH0[3]);
                    mma16816h(oacc[2 * dt + 2], pL, vH1[0], vH1[1]);
                    mma16816h(oacc[2 * dt + 3], pL, vH1[2], vH1[3]);
                }
            }
        }
        __syncthreads();
    }

    // output: fp16 hi/lo, [S][HQ*HD]
    {
        float inv0 = 1.0f / larr[Rp + rl];
        float inv1 = 1.0f / larr[Rp + 8 + rl];
        const int r0 = q0 + Rp + rl;
#pragma unroll
        for (int n8 = 0; n8 < 16; n8++) {
            int col = h * HD + Dq + n8 * 8 + (lane & 3) * 2;
            float o0 = oacc[n8][0] * inv0, o1 = oacc[n8][1] * inv0;
            float o2 = oacc[n8][2] * inv1, o3 = oacc[n8][3] * inv1;
            uint32_t h0 = pack2h(o0, o1);
            __half2 hv0 = *(__half2*)&h0;
            uint32_t l0 = pack2h(o0 - __half2float(hv0.x), o1 - __half2float(hv0.y));
            uint32_t h1 = pack2h(o2, o3);
            __half2 hv1 = *(__half2*)&h1;
            uint32_t l1 = pack2h(o2 - __half2float(hv1.x), o3 - __half2float(hv1.y));
            *(uint32_t*)(AOh + (size_t)r0 * (HQ * HD) + col) = h0;
            *(uint32_t*)(AOl + (size_t)r0 * (HQ * HD) + col) = l0;
            *(uint32_t*)(AOh + (size_t)(r0 + 8) * (HQ * HD) + col) = h1;
            *(uint32_t*)(AOl + (size_t)(r0 + 8) * (HQ * HD) + col) = l1;
        }
    }
}

// ================= launch =================
extern "C" void kernel_launch(void* const* d_in, const int* in_sizes, int n_in,
                              void* d_out, int out_size) {
    const float* hidden = (const float*)d_in[0];
    const float* cosb   = (const float*)d_in[1];
    const float* sinb   = (const float*)d_in[2];
    // d_in[3] = attention_mask (sliding window, implemented analytically)
    const float* Wq = (const float*)d_in[4];
    const float* Wk = (const float*)d_in[5];
    const float* Wv = (const float*)d_in[6];
    const float* Wo = (const float*)d_in[7];
    const float* qw = (const float*)d_in[8];
    const float* kw = (const float*)d_in[9];
    float* out = (float*)d_out;

    float *QKp, *Vp;
    cudaGetSymbolAddress((void**)&QKp, g_QKp);
    cudaGetSymbolAddress((void**)&Vp, g_Vp);

    int8_t *hq1, *hq2, *wqk1, *wqk2, *wv1, *wv2;
    float *sh, *swqk, *swv;
    cudaGetSymbolAddress((void**)&hq1, g_hq1);
    cudaGetSymbolAddress((void**)&hq2, g_hq2);
    cudaGetSymbolAddress((void**)&sh, g_sh);
    cudaGetSymbolAddress((void**)&wqk1, g_wqk1);
    cudaGetSymbolAddress((void**)&wqk2, g_wqk2);
    cudaGetSymbolAddress((void**)&swqk, g_swqk);
    cudaGetSymbolAddress((void**)&wv1, g_wv1);
    cudaGetSymbolAddress((void**)&wv2, g_wv2);
    cudaGetSymbolAddress((void**)&swv, g_swv);

    __half *wof, *aofh, *aofl, *vrf;
    __nv_bfloat16 *qrh, *qrl, *krh, *krl;
    cudaGetSymbolAddress((void**)&wof, g_wo_f);
    cudaGetSymbolAddress((void**)&aofh, g_ao_fh);
    cudaGetSymbolAddress((void**)&aofl, g_ao_fl);
    cudaGetSymbolAddress((void**)&qrh, g_qr_h);
    cudaGetSymbolAddress((void**)&qrl, g_qr_l);
    cudaGetSymbolAddress((void**)&krh, g_kr_h);
    cudaGetSymbolAddress((void**)&krl, g_kr_l);
    cudaGetSymbolAddress((void**)&vrf, g_vr_f);

    cudaFuncSetAttribute((const void*)gemm_s8x3,
                         cudaFuncAttributeMaxDynamicSharedMemorySize, SMEM_GEMM);
    cudaFuncSetAttribute((const void*)gemm_fp16x2,
                         cudaFuncAttributeMaxDynamicSharedMemorySize, SMEM_GEMM_F);
    cudaFuncSetAttribute((const void*)attn_mma,
                         cudaFuncAttributeMaxDynamicSharedMemorySize, SMEM_ATTN);

    // quantize hid / Wq|Wk / Wv rows to two-digit int8; Wo -> fp16
    quant_rows<<<QROWS, 256>>>(hidden, Wq, Wk, Wv,
                               hq1, hq2, sh, wqk1, wqk2, swqk, wv1, wv2, swv);
    cvt_wo<<<(N4_WO + 255) / 256, 256>>>((const float4*)Wo, wof);

    // combined Q|K projection: int8 3-term
    gemm_s8x3<<<dim3(NQK / 128, 64), 128, SMEM_GEMM>>>(hq1, hq2, wqk1, wqk2,
                                                       sh, swqk, QKp, NQK, H_DIM);
    // V projection: int8 3-term (reuses hid digits)
    gemm_s8x3<<<dim3(8, 64), 128, SMEM_GEMM>>>(hq1, hq2, wv1, wv2,
                                               sh, swv, Vp, HKV * HD, H_DIM);

    // RMSNorm + RoPE (warp-per-head, sync-free)
    norm_rope3<<<S_LEN, 256>>>(QKp, Vp, cosb, sinb, qw, kw,
                               qrh, qrl, krh, krl, vrf);

    // tensor-core flash attention -> fp16 hi/lo AO (heavy-first order)
    attn_mma<<<dim3(S_LEN / 64, HQ), 256, SMEM_ATTN>>>(qrh, qrl, krh, krl, vrf, aofh, aofl);

    // output projection: fp16 2-term
    gemm_fp16x2<<<dim3(16, 64), 128, SMEM_GEMM_F>>>(aofh, aofl, wof, out, H_DIM, H_DIM);
}